// round 12
// baseline (speedup 1.0000x reference)
#include <cuda_runtime.h>

#define BB 8
#define DD 64
#define KK 32
#define HW 3136          // 56*56
#define HALF (HW/2)      // 1568
#define LOG2E 1.4426950408889634f

// Scratch (allocation-free rule: __device__ globals, rewritten every replay)
__device__ float g_EMp[BB * DD * 2];   // per-half-row partial sums of E
__device__ float g_gp1[BB * DD];       // 1 + gamma

__device__ __forceinline__ float fast_ex2(float x) {
    float y; asm("ex2.approx.ftz.f32 %0, %1;" : "=f"(y) : "f"(x)); return y;
}
__device__ __forceinline__ float fast_rcp(float x) {
    float y; asm("rcp.approx.ftz.f32 %0, %1;" : "=f"(y) : "f"(x)); return y;
}

// ───────────────────────── Kernel 1: main ─────────────────────────
// grid = BB*DD*2 CTAs, 128 threads. CTA (bd, half) computes
// E[b,d,n] = x - (Σ_k e_k c_k)/(Σ_k e_k),  e_k = exp(s_k (x-c_k)^2)
// using expanded exponent A x^2 + B x + C (4 fma-ops + 1 MUFU per k).
// scale<=0 => logits<=0 => single-pass softmax is safe.
__global__ __launch_bounds__(128, 3) void enc_main_kernel(
    const float* __restrict__ X,
    const float* __restrict__ codewords,
    const float* __restrict__ scale,
    float* __restrict__ outE)
{
    const int blk  = blockIdx.x;
    const int bd   = blk >> 1;
    const int half = blk & 1;
    const int d    = bd & (DD - 1);

    const float* __restrict__ xp = X    + (size_t)bd * HW + half * HALF;
    float* __restrict__       ep = outE + (size_t)bd * HW + half * HALF;

    float A[KK], B[KK], C[KK], Ck[KK];
#pragma unroll
    for (int k = 0; k < KK; k++) {
        float c  = codewords[k * DD + d];
        float st = scale[k * DD + d] * LOG2E;
        A[k]  = st;
        B[k]  = -2.0f * st * c;
        C[k]  = st * c * c;
        Ck[k] = c;
    }

    float local = 0.0f;
    for (int n = threadIdx.x; n < HALF; n += 128) {
        const float x  = xp[n];
        const float x2 = x * x;
        float den = 0.0f, cm = 0.0f;
#pragma unroll
        for (int k = 0; k < KK; k++) {
            float w  = fmaf(B[k], x, C[k]);
            float v  = fmaf(A[k], x2, w);     // log2(e_k), <= ~0
            float e2 = fast_ex2(v);
            den += e2;
            cm = fmaf(e2, Ck[k], cm);
        }
        float e = fmaf(-cm, fast_rcp(den), x);  // x - cm/den
        ep[n] = e;
        local += e;
    }

    // warp + smem reduce of the partial EM sum
    const int lane = threadIdx.x & 31, warp = threadIdx.x >> 5;
#pragma unroll
    for (int off = 16; off > 0; off >>= 1)
        local += __shfl_xor_sync(0xffffffff, local, off);
    __shared__ float red[4];
    if (lane == 0) red[warp] = local;
    __syncthreads();
    if (threadIdx.x == 0)
        g_EMp[blk] = red[0] + red[1] + red[2] + red[3];
}

// ───────────────────────── Kernel 2: gamma ─────────────────────────
// One block, 512 threads. Thread t=(b,d) computes
// g_gp1[t] = 1 + sigmoid( EM[b,:] . fc_w[d,:] + fc_b[d] ).
__global__ __launch_bounds__(512) void enc_gamma_kernel(
    const float* __restrict__ fc_w,
    const float* __restrict__ fc_b)
{
    __shared__ float sEM[BB * DD];
    __shared__ float sW[DD * 65];        // padded to kill bank conflicts
    const int t = threadIdx.x;

    sEM[t] = (g_EMp[2 * t] + g_EMp[2 * t + 1]) * (1.0f / (float)KK);
#pragma unroll
    for (int i = 0; i < 8; i++) {        // 4096 floats, coalesced
        int idx = t + i * 512;
        sW[(idx >> 6) * 65 + (idx & 63)] = fc_w[idx];
    }
    __syncthreads();

    const int b = t >> 6, d = t & 63;
    float a0 = fc_b[d], a1 = 0.f, a2 = 0.f, a3 = 0.f;
#pragma unroll
    for (int j = 0; j < DD; j += 4) {
        a0 = fmaf(sEM[b * DD + j + 0], sW[d * 65 + j + 0], a0);
        a1 = fmaf(sEM[b * DD + j + 1], sW[d * 65 + j + 1], a1);
        a2 = fmaf(sEM[b * DD + j + 2], sW[d * 65 + j + 2], a2);
        a3 = fmaf(sEM[b * DD + j + 3], sW[d * 65 + j + 3], a3);
    }
    float acc = (a0 + a1) + (a2 + a3);
    float g = fast_rcp(1.0f + fast_ex2(-acc * LOG2E));   // sigmoid
    g_gp1[t] = 1.0f + g;
}

// ───────────────────────── Kernel 3: scale+relu ─────────────────────────
// Pure streaming: grid = 1024 CTAs x 128 threads, barrier-free.
__global__ __launch_bounds__(128) void enc_scale_kernel(float* __restrict__ out)
{
    const int blk  = blockIdx.x;
    const int bd   = blk >> 1;
    const int half = blk & 1;
    const float gm = g_gp1[bd];          // broadcast load

    float4* __restrict__ p = (float4*)(out + (size_t)bd * HW + half * HALF);
    const int n4 = HALF / 4;             // 392
#pragma unroll
    for (int i = threadIdx.x; i < n4; i += 128) {
        float4 v = p[i];
        v.x = fmaxf(v.x * gm, 0.0f);
        v.y = fmaxf(v.y * gm, 0.0f);
        v.z = fmaxf(v.z * gm, 0.0f);
        v.w = fmaxf(v.w * gm, 0.0f);
        p[i] = v;
    }
}

extern "C" void kernel_launch(void* const* d_in, const int* in_sizes, int n_in,
                              void* d_out, int out_size) {
    const float* X    = (const float*)d_in[0];
    const float* cw   = (const float*)d_in[1];
    const float* sc   = (const float*)d_in[2];
    const float* fc_w = (const float*)d_in[3];
    const float* fc_b = (const float*)d_in[4];
    float* out = (float*)d_out;

    enc_main_kernel <<<BB * DD * 2, 128>>>(X, cw, sc, out);
    enc_gamma_kernel<<<1, 512>>>(fc_w, fc_b);
    enc_scale_kernel<<<BB * DD * 2, 128>>>(out);
}

// round 13
// speedup vs baseline: 1.0714x; 1.0714x over previous
#include <cuda_runtime.h>

#define BB 8
#define DD 64
#define KK 32
#define HW 3136          // 56*56
#define LOG2E 1.4426950408889634f

// Scratch (allocation-free rule: __device__ globals, rewritten every replay)
__device__ float g_EM[BB * DD];     // EM[b,d]
__device__ float g_gp1[BB * DD];    // 1 + gamma

__device__ __forceinline__ float fast_ex2(float x) {
    float y; asm("ex2.approx.ftz.f32 %0, %1;" : "=f"(y) : "f"(x)); return y;
}
__device__ __forceinline__ float fast_rcp(float x) {
    float y; asm("rcp.approx.ftz.f32 %0, %1;" : "=f"(y) : "f"(x)); return y;
}

// ───────────────────────── Kernel 1: main ─────────────────────────
// One CTA per (b,d) row, 256 threads, 2 n-values per thread per iter.
// E[b,d,n] = x - (Σ_k e_k c_k)/(Σ_k e_k), e_k = exp2(A x² + B x + C),
// A = s·log2e, B = -2Ac, C = Ac². scale ≤ 0 ⇒ logits ≤ 0 ⇒ single-pass safe.
// Per-k constants live in smem as float4 {A,B,C,c}: 1 broadcast LDS.128/k.
__global__ __launch_bounds__(256) void enc_main_kernel(
    const float* __restrict__ X,
    const float* __restrict__ codewords,
    const float* __restrict__ scale,
    float* __restrict__ outE)
{
    __shared__ float4 kc[KK];
    const int bd = blockIdx.x;
    const int d  = bd & (DD - 1);

    if (threadIdx.x < KK) {
        const int k = threadIdx.x;
        float c  = codewords[k * DD + d];
        float st = scale[k * DD + d] * LOG2E;
        kc[k] = make_float4(st, -2.0f * st * c, st * c * c, c);
    }
    __syncthreads();

    const float2* __restrict__ xp2 = (const float2*)(X    + (size_t)bd * HW);
    float2* __restrict__       ep2 = (float2*)      (outE + (size_t)bd * HW);

    float local = 0.0f;
    for (int i = threadIdx.x; i < HW / 2; i += 256) {   // 1568 float2's
        const float2 xv = xp2[i];
        const float x0 = xv.x,      x1 = xv.y;
        const float q0 = x0 * x0,   q1 = x1 * x1;
        float den0 = 0.f, den1 = 0.f, cm0 = 0.f, cm1 = 0.f;
#pragma unroll
        for (int k = 0; k < KK; k++) {
            const float4 kk = kc[k];
            float v0 = fmaf(kk.x, q0, fmaf(kk.y, x0, kk.z));
            float v1 = fmaf(kk.x, q1, fmaf(kk.y, x1, kk.z));
            float e0 = fast_ex2(v0);
            float e1 = fast_ex2(v1);
            den0 += e0;                 den1 += e1;
            cm0 = fmaf(e0, kk.w, cm0);  cm1 = fmaf(e1, kk.w, cm1);
        }
        float2 ev;
        ev.x = fmaf(-cm0, fast_rcp(den0), x0);
        ev.y = fmaf(-cm1, fast_rcp(den1), x1);
        ep2[i] = ev;
        local += ev.x + ev.y;
    }

    // Reduce EM partial across the CTA
    const int lane = threadIdx.x & 31, warp = threadIdx.x >> 5;
#pragma unroll
    for (int off = 16; off > 0; off >>= 1)
        local += __shfl_xor_sync(0xffffffff, local, off);
    __shared__ float red[8];
    if (lane == 0) red[warp] = local;
    __syncthreads();
    if (threadIdx.x == 0) {
        float s = 0.f;
#pragma unroll
        for (int w = 0; w < 8; w++) s += red[w];
        g_EM[bd] = s * (1.0f / (float)KK);
    }
}

// ───────────────────────── Kernel 2: gamma ─────────────────────────
// One block, 512 threads: thread t=(b,d) → g_gp1[t] = 1 + sigmoid(EM[b,:]·fc_w[d,:] + fc_b[d])
__global__ __launch_bounds__(512) void enc_gamma_kernel(
    const float* __restrict__ fc_w,
    const float* __restrict__ fc_b)
{
    __shared__ float sEM[BB * DD];
    __shared__ float sW[DD * 65];          // padded rows: no bank conflicts
    const int t = threadIdx.x;

    sEM[t] = g_EM[t];
#pragma unroll
    for (int i = 0; i < 8; i++) {
        int idx = t + i * 512;
        sW[(idx >> 6) * 65 + (idx & 63)] = fc_w[idx];
    }
    __syncthreads();

    const int b = t >> 6, d = t & 63;
    float a0 = fc_b[d], a1 = 0.f, a2 = 0.f, a3 = 0.f;
#pragma unroll
    for (int j = 0; j < DD; j += 4) {
        a0 = fmaf(sEM[b * DD + j + 0], sW[d * 65 + j + 0], a0);
        a1 = fmaf(sEM[b * DD + j + 1], sW[d * 65 + j + 1], a1);
        a2 = fmaf(sEM[b * DD + j + 2], sW[d * 65 + j + 2], a2);
        a3 = fmaf(sEM[b * DD + j + 3], sW[d * 65 + j + 3], a3);
    }
    float acc = (a0 + a1) + (a2 + a3);
    float g = fast_rcp(1.0f + fast_ex2(-acc * LOG2E));   // sigmoid
    g_gp1[t] = 1.0f + g;
}

// ───────────────────────── Kernel 3: scale+relu ─────────────────────────
// Pure streaming, barrier-free: 1024 CTAs × 128 threads, float4 in-place.
__global__ __launch_bounds__(128) void enc_scale_kernel(float* __restrict__ out)
{
    const int blk  = blockIdx.x;
    const int bd   = blk >> 1;
    const int half = blk & 1;
    const float gm = g_gp1[bd];

    float4* __restrict__ p = (float4*)(out + (size_t)bd * HW + half * (HW / 2));
    const int n4 = HW / 8;                // 392 float4's per half-row
#pragma unroll
    for (int i = threadIdx.x; i < n4; i += 128) {
        float4 v = p[i];
        v.x = fmaxf(v.x * gm, 0.0f);
        v.y = fmaxf(v.y * gm, 0.0f);
        v.z = fmaxf(v.z * gm, 0.0f);
        v.w = fmaxf(v.w * gm, 0.0f);
        p[i] = v;
    }
}

extern "C" void kernel_launch(void* const* d_in, const int* in_sizes, int n_in,
                              void* d_out, int out_size) {
    const float* X    = (const float*)d_in[0];
    const float* cw   = (const float*)d_in[1];
    const float* sc   = (const float*)d_in[2];
    const float* fc_w = (const float*)d_in[3];
    const float* fc_b = (const float*)d_in[4];
    float* out = (float*)d_out;

    enc_main_kernel <<<BB * DD, 256>>>(X, cw, sc, out);
    enc_gamma_kernel<<<1, 512>>>(fc_w, fc_b);
    enc_scale_kernel<<<BB * DD * 2, 128>>>(out);
}

// round 14
// speedup vs baseline: 1.3556x; 1.2653x over previous
#include <cuda_runtime.h>
#include <cstdint>

#define BB 8
#define DD 64
#define KK 32
#define HW 3136          // 56*56
#define LOG2E 1.4426950408889634f

// Scratch (allocation-free rule: __device__ globals, rewritten every replay)
__device__ float g_EM[BB * DD];     // EM[b,d]
__device__ float g_gp1[BB * DD];    // 1 + gamma

__device__ __forceinline__ float fast_ex2(float x) {
    float y; asm("ex2.approx.ftz.f32 %0, %1;" : "=f"(y) : "f"(x)); return y;
}
__device__ __forceinline__ float fast_rcp(float x) {
    float y; asm("rcp.approx.ftz.f32 %0, %1;" : "=f"(y) : "f"(x)); return y;
}

// ───────────────────────── Kernel 1: main ─────────────────────────
// One CTA per (b,d) row, 256 threads, 2 n-values per thread-iter.
// E[b,d,n] = x - (Σ_k e_k c_k)/(Σ_k e_k), e_k = exp2(A x² + B x + C),
// A = s·log2e, B = -2Ac, C = Ac². scale ≤ 0 ⇒ logits ≤ 0 ⇒ single-pass safe.
// Per-k constants in smem; re-fetched each n-iter via asm-volatile LDS.128 so
// ptxas CANNOT hoist them into 128 registers (the R11/R12 occupancy killer).
__global__ __launch_bounds__(256) void enc_main_kernel(
    const float* __restrict__ X,
    const float* __restrict__ codewords,
    const float* __restrict__ scale,
    float* __restrict__ outE)
{
    __shared__ float4 kc[KK];
    const int bd = blockIdx.x;
    const int d  = bd & (DD - 1);

    if (threadIdx.x < KK) {
        const int k = threadIdx.x;
        float c  = codewords[k * DD + d];
        float st = scale[k * DD + d] * LOG2E;
        kc[k] = make_float4(st, -2.0f * st * c, st * c * c, c);
    }
    __syncthreads();

    const uint32_t kc_base = (uint32_t)__cvta_generic_to_shared(kc);

    const float2* __restrict__ xp2 = (const float2*)(X    + (size_t)bd * HW);
    float2* __restrict__       ep2 = (float2*)      (outE + (size_t)bd * HW);

    float local = 0.0f;
    for (int i = threadIdx.x; i < HW / 2; i += 256) {   // 1568 float2's
        const float2 xv = xp2[i];
        const float x0 = xv.x,      x1 = xv.y;
        const float q0 = x0 * x0,   q1 = x1 * x1;
        float den0 = 0.f, den1 = 0.f, cm0 = 0.f, cm1 = 0.f;
#pragma unroll
        for (int k = 0; k < KK; k++) {
            float A, B, C, c;
            asm volatile("ld.shared.v4.f32 {%0,%1,%2,%3}, [%4];"
                         : "=f"(A), "=f"(B), "=f"(C), "=f"(c)
                         : "r"(kc_base + k * 16));
            float w0 = fmaf(B, x0, C);
            float w1 = fmaf(B, x1, C);
            float v0 = fmaf(A, q0, w0);
            float v1 = fmaf(A, q1, w1);
            float e0 = fast_ex2(v0);
            float e1 = fast_ex2(v1);
            den0 += e0;                den1 += e1;
            cm0 = fmaf(e0, c, cm0);    cm1 = fmaf(e1, c, cm1);
        }
        float2 ev;
        ev.x = fmaf(-cm0, fast_rcp(den0), x0);
        ev.y = fmaf(-cm1, fast_rcp(den1), x1);
        ep2[i] = ev;
        local += ev.x + ev.y;
    }

    // Reduce EM partial across the CTA
    const int lane = threadIdx.x & 31, warp = threadIdx.x >> 5;
#pragma unroll
    for (int off = 16; off > 0; off >>= 1)
        local += __shfl_xor_sync(0xffffffff, local, off);
    __shared__ float red[8];
    if (lane == 0) red[warp] = local;
    __syncthreads();
    if (threadIdx.x == 0) {
        float s = 0.f;
#pragma unroll
        for (int w = 0; w < 8; w++) s += red[w];
        g_EM[bd] = s * (1.0f / (float)KK);
    }
}

// ───────────────────────── Kernel 2: gamma ─────────────────────────
// One block, 512 threads: thread t=(b,d) → g_gp1[t] = 1 + sigmoid(EM[b,:]·fc_w[d,:] + fc_b[d])
__global__ __launch_bounds__(512) void enc_gamma_kernel(
    const float* __restrict__ fc_w,
    const float* __restrict__ fc_b)
{
    __shared__ float sEM[BB * DD];
    __shared__ float sW[DD * 65];          // padded rows: no bank conflicts
    const int t = threadIdx.x;

    sEM[t] = g_EM[t];
#pragma unroll
    for (int i = 0; i < 8; i++) {
        int idx = t + i * 512;
        sW[(idx >> 6) * 65 + (idx & 63)] = fc_w[idx];
    }
    __syncthreads();

    const int b = t >> 6, d = t & 63;
    float a0 = fc_b[d], a1 = 0.f, a2 = 0.f, a3 = 0.f;
#pragma unroll
    for (int j = 0; j < DD; j += 4) {
        a0 = fmaf(sEM[b * DD + j + 0], sW[d * 65 + j + 0], a0);
        a1 = fmaf(sEM[b * DD + j + 1], sW[d * 65 + j + 1], a1);
        a2 = fmaf(sEM[b * DD + j + 2], sW[d * 65 + j + 2], a2);
        a3 = fmaf(sEM[b * DD + j + 3], sW[d * 65 + j + 3], a3);
    }
    float acc = (a0 + a1) + (a2 + a3);
    float g = fast_rcp(1.0f + fast_ex2(-acc * LOG2E));   // sigmoid
    g_gp1[t] = 1.0f + g;
}

// ───────────────────────── Kernel 3: scale+relu ─────────────────────────
// Loop-free streaming: 3136 CTAs × 128 threads, exactly one float4 per thread.
// E is L2-resident from kernel 1 (12.8 MB << 126 MB L2).
__global__ __launch_bounds__(128) void enc_scale_kernel(float* __restrict__ out)
{
    const int idx = blockIdx.x * 128 + threadIdx.x;   // 0 .. 401407 float4's
    const int bd  = idx / (HW / 4);                   // 784 float4's per row
    const float gm = g_gp1[bd];

    float4* __restrict__ p = (float4*)out;
    float4 v = p[idx];
    v.x = fmaxf(v.x * gm, 0.0f);
    v.y = fmaxf(v.y * gm, 0.0f);
    v.z = fmaxf(v.z * gm, 0.0f);
    v.w = fmaxf(v.w * gm, 0.0f);
    p[idx] = v;
}

extern "C" void kernel_launch(void* const* d_in, const int* in_sizes, int n_in,
                              void* d_out, int out_size) {
    const float* X    = (const float*)d_in[0];
    const float* cw   = (const float*)d_in[1];
    const float* sc   = (const float*)d_in[2];
    const float* fc_w = (const float*)d_in[3];
    const float* fc_b = (const float*)d_in[4];
    float* out = (float*)d_out;

    enc_main_kernel <<<BB * DD, 256>>>(X, cw, sc, out);
    enc_gamma_kernel<<<1, 512>>>(fc_w, fc_b);
    enc_scale_kernel<<<(BB * DD * HW) / (4 * 128), 128>>>(out);
}